// round 8
// baseline (speedup 1.0000x reference)
#include <cuda_runtime.h>

#define LSEQ 768
#define NSEQ 256
#define MD   256
#define MSAD 23
#define SEQD 22
#define ZD   128
#define NB   14
#define RC   32
#define PQ   92      // floats per pair: 23 k * 4 (dup-quad)

// Scratch: kb[i,:] = seq@Wk + bk + bpos  (384 KB)
__device__ float g_kb[LSEQ * ZD];

// ---- packed f32x2 helpers (sm_103a, PTX-only) ----
typedef unsigned long long ull;
__device__ __forceinline__ ull pk2(float a, float b) {
    ull r; asm("mov.b64 %0, {%1, %2};" : "=l"(r) : "f"(a), "f"(b)); return r;
}
__device__ __forceinline__ ull fma2(ull a, ull b, ull c) {
    ull d; asm("fma.rn.f32x2 %0, %1, %2, %3;" : "=l"(d) : "l"(a), "l"(b), "l"(c));
    return d;
}
__device__ __forceinline__ ull add2(ull a, ull b) {
    ull d; asm("add.rn.f32x2 %0, %1, %2;" : "=l"(d) : "l"(a), "l"(b)); return d;
}
__device__ __forceinline__ void st2cs(float* p, ull a, ull b) {
    asm volatile("st.global.cs.v2.u64 [%0], {%1, %2};" :: "l"(p), "l"(a), "l"(b) : "memory");
}
__device__ __forceinline__ float4 ld4(const float* p) {
    return *reinterpret_cast<const float4*>(p);
}
__device__ __forceinline__ unsigned smem_u32(const void* p) {
    unsigned a;
    asm("{ .reg .u64 t; cvta.to.shared.u64 t, %1; cvt.u32.u64 %0, t; }" : "=r"(a) : "l"(p));
    return a;
}
__device__ __forceinline__ void cpasync4(unsigned dst, const float* src) {
    asm volatile("cp.async.ca.shared.global [%0], [%1], 4;" :: "r"(dst), "l"(src));
}

// ---------------------------------------------------------------------------
// kb precompute: 2 rows per 256-thread block.
// ---------------------------------------------------------------------------
__global__ __launch_bounds__(256) void kbkern(
    const float* __restrict__ seq, const float* __restrict__ Wk,
    const float* __restrict__ bk,  const float* __restrict__ bpos)
{
    const int tid = threadIdx.x;
    const int rr  = tid >> 7;
    const int c   = tid & 127;
    const int i   = blockIdx.x * 2 + rr;

    __shared__ float s[2][SEQD];
    if (tid < 2 * SEQD)
        s[tid / SEQD][tid % SEQD] = seq[(blockIdx.x * 2 + tid / SEQD) * SEQD + tid % SEQD];
    __syncthreads();

    float a = bk[c] + bpos[c];
    #pragma unroll
    for (int d = 0; d < SEQD; d++) a += s[rr][d] * Wk[d * ZD + c];
    g_kb[i * ZD + c] = a;
}

// ---------------------------------------------------------------------------
// Fused main kernel: 1536 blocks x 128 threads, strict 1:1 interleave.
//   b & 1 == 0 -> m-path (l = b>>1, all 256 rows)
//   b & 1 == 1 -> z-path (4 j's, quarter of the i range)
// ---------------------------------------------------------------------------
__global__ __launch_bounds__(128, 4) void mainkern(
    const float* __restrict__ seq,  const float* __restrict__ msa,
    const float* __restrict__ Wmsa, const float* __restrict__ bmsa,
    const float* __restrict__ Ws,   const float* __restrict__ bs,
    const float* __restrict__ Wq,   const float* __restrict__ bq,
    const float* __restrict__ Wpos, const float* __restrict__ Wpos2,
    const float* __restrict__ bpos2,
    float* __restrict__ outm, float* __restrict__ outz)
{
    const int b   = blockIdx.x;
    const int tid = threadIdx.x;

    if (b & 1) {
        // ------------- z-path: z[i,j,:] = sq[j] + kb[i] + Wpos[rel] ---------
        const int zid = b >> 1;           // 0..767
        const int j   = (zid >> 2) * 4 + (tid >> 5);
        const int iq  = zid & 3;          // i-quarter
        const int c   = (tid & 31) * 4;

        float4 q;
        q.x = bq[c]; q.y = bq[c + 1]; q.z = bq[c + 2]; q.w = bq[c + 3];
        #pragma unroll
        for (int d = 0; d < SEQD; d++) {
            const float  sv = seq[j * SEQD + d];
            const float4 w  = ld4(Wq + d * ZD + c);
            q.x += sv * w.x; q.y += sv * w.y; q.z += sv * w.z; q.w += sv * w.w;
        }
        const ull q01 = pk2(q.x, q.y);
        const ull q23 = pk2(q.z, q.w);

        const int i0 = iq * (LSEQ / 4);
        for (int ib = i0; ib < i0 + LSEQ / 4; ib += 8) {
            // batch 8 independent kb loads (MLP=8 over L2 latency)
            ulonglong2 kbv[8];
            #pragma unroll
            for (int u = 0; u < 8; u++)
                kbv[u] = *reinterpret_cast<const ulonglong2*>(&g_kb[(ib + u) * ZD + c]);
            #pragma unroll
            for (int u = 0; u < 8; u++) {
                const int i = ib + u;
                int rel = j - i;
                rel = min(max(rel, -RC), RC) + RC;
                const ulonglong2 wp = *reinterpret_cast<const ulonglong2*>(&Wpos[rel * ZD + c]);
                const ull o01 = add2(add2(q01, kbv[u].x), wp.x);
                const ull o23 = add2(add2(q23, kbv[u].y), wp.y);
                st2cs(&outz[((long)i * LSEQ + j) * ZD + c], o01, o23);
            }
        }
        return;
    }

    // ------------ m-path: m[n,l,:] = msa[n,l,:]@Wmsa + sp[l,:] --------------
    const int l  = b >> 1;                // 0..767
    const int rg = tid >> 6;              // 0..1
    const int c  = (tid & 63) * 4;

    // Dup-quad layout: pairs[p][k] = {m[2p,k], m[2p,k], m[2p+1,k], m[2p+1,k]}
    // One broadcast LDS.128 yields both fma2 multiplier operands.
    __shared__ float pairs[(NSEQ / 2) * PQ];   // 47.1 KB
    __shared__ float srow[SEQD];

    if (tid < SEQD) srow[tid] = seq[l * SEQD + tid];
    // cp.async fill: each element duplicated into two adjacent slots
    for (int idx = tid; idx < NSEQ * MSAD; idx += 128) {
        const int n = idx / MSAD;
        const int k = idx - n * MSAD;
        const float* src = &msa[(n * LSEQ + l) * MSAD + k];
        const unsigned dst = smem_u32(&pairs[(n >> 1) * PQ + 4 * k + 2 * (n & 1)]);
        cpasync4(dst,     src);
        cpasync4(dst + 4, src);
    }
    asm volatile("cp.async.commit_group;" ::: "memory");

    // per-thread weights, channel-packed f32x2 (92 regs) — overlaps cp.async
    ull w0[MSAD], w1[MSAD];
    #pragma unroll
    for (int k = 0; k < MSAD; k++) {
        const float4 w = ld4(Wmsa + k * MD + c);
        w0[k] = pk2(w.x, w.y);
        w1[k] = pk2(w.z, w.w);
    }

    // sp[l, c..c+3]
    float4 sp;
    sp.x = bs[c]     + bpos2[c]     + bmsa[c];
    sp.y = bs[c + 1] + bpos2[c + 1] + bmsa[c + 1];
    sp.z = bs[c + 2] + bpos2[c + 2] + bmsa[c + 2];
    sp.w = bs[c + 3] + bpos2[c + 3] + bmsa[c + 3];
    #pragma unroll
    for (int bb = 0; bb < NB; bb++)
        if ((l >> bb) & 1) {
            const float4 w = ld4(Wpos2 + bb * MD + c);
            sp.x += w.x; sp.y += w.y; sp.z += w.z; sp.w += w.w;
        }
    asm volatile("cp.async.wait_group 0;" ::: "memory");
    __syncthreads();
    #pragma unroll
    for (int d = 0; d < SEQD; d++) {
        const float  sv = srow[d];
        const float4 w  = ld4(Ws + d * MD + c);
        sp.x += sv * w.x; sp.y += sv * w.y; sp.z += sv * w.z; sp.w += sv * w.w;
    }
    const ull sp01 = pk2(sp.x, sp.y);
    const ull sp23 = pk2(sp.z, sp.w);

    // main loop: one row-PAIR per iteration -> 4 independent fma2 chains,
    // 23 broadcast LDS.128, ZERO movs.
    for (int it = 0; it < NSEQ / 4; it++) {
        const int p  = it * 2 + rg;       // pair index 0..127
        const int na = p * 2;             // rows na, na+1
        const float* base = &pairs[p * PQ];

        ull a01 = sp01, a23 = sp23;       // row na
        ull b01 = sp01, b23 = sp23;       // row na+1
        #pragma unroll
        for (int k = 0; k < MSAD; k++) {
            const ulonglong2 d = *reinterpret_cast<const ulonglong2*>(base + 4 * k);
            a01 = fma2(w0[k], d.x, a01);  // d.x = {va,va}
            a23 = fma2(w1[k], d.x, a23);
            b01 = fma2(w0[k], d.y, b01);  // d.y = {vb,vb}
            b23 = fma2(w1[k], d.y, b23);
        }
        st2cs(&outm[((long)na * LSEQ + l) * MD + c], a01, a23);
        st2cs(&outm[((long)(na + 1) * LSEQ + l) * MD + c], b01, b23);
    }
}

// ---------------------------------------------------------------------------
extern "C" void kernel_launch(void* const* d_in, const int* in_sizes, int n_in,
                              void* d_out, int out_size)
{
    const float* seq   = (const float*)d_in[0];
    const float* msa   = (const float*)d_in[1];
    const float* Wmsa  = (const float*)d_in[2];
    const float* bmsa  = (const float*)d_in[3];
    const float* Ws    = (const float*)d_in[4];
    const float* bs    = (const float*)d_in[5];
    const float* Wq    = (const float*)d_in[6];
    const float* bq    = (const float*)d_in[7];
    const float* Wk    = (const float*)d_in[8];
    const float* bk    = (const float*)d_in[9];
    const float* Wpos  = (const float*)d_in[10];
    const float* bpos  = (const float*)d_in[11];
    const float* Wpos2 = (const float*)d_in[12];
    const float* bpos2 = (const float*)d_in[13];

    float* outm = (float*)d_out;
    float* outz = outm + (long)NSEQ * LSEQ * MD;

    kbkern<<<LSEQ / 2, 256>>>(seq, Wk, bk, bpos);
    mainkern<<<1536, 128>>>(seq, msa, Wmsa, bmsa, Ws, bs, Wq, bq,
                            Wpos, Wpos2, bpos2, outm, outz);
}

// round 9
// speedup vs baseline: 1.0733x; 1.0733x over previous
#include <cuda_runtime.h>

#define LSEQ 768
#define NSEQ 256
#define MD   256
#define MSAD 23
#define SEQD 22
#define ZD   128
#define NB   14
#define RC   32
#define PSTRIDE 48     // floats per row-pair in smem: 23 k * 2 + pad
#define MU_ROWS 64     // rows per m-unit
#define NPAIR   32     // pairs per m-unit
#define ZCH     48     // i's per z-unit
#define NCTA    592    // 4 CTAs x 148 SMs, exact residency
// units: 3072 m + 3072 z = 6144, global list alternates (even=m, odd=z)
// 6144 = 592*10 + 224 -> first 224 CTAs take 11 units, rest 10.

// Scratch: kb[i,:] = seq@Wk + bk + bpos  (384 KB)
__device__ float g_kb[LSEQ * ZD];

// ---- packed f32x2 helpers (sm_103a, PTX-only) ----
typedef unsigned long long ull;
__device__ __forceinline__ ull pk2(float a, float b) {
    ull r; asm("mov.b64 %0, {%1, %2};" : "=l"(r) : "f"(a), "f"(b)); return r;
}
__device__ __forceinline__ ull dup2(float a) {
    ull r; asm("mov.b64 %0, {%1, %1};" : "=l"(r) : "f"(a)); return r;
}
__device__ __forceinline__ ull fma2(ull a, ull b, ull c) {
    ull d; asm("fma.rn.f32x2 %0, %1, %2, %3;" : "=l"(d) : "l"(a), "l"(b), "l"(c));
    return d;
}
__device__ __forceinline__ ull add2(ull a, ull b) {
    ull d; asm("add.rn.f32x2 %0, %1, %2;" : "=l"(d) : "l"(a), "l"(b)); return d;
}
__device__ __forceinline__ void st2cs(float* p, ull a, ull b) {
    asm volatile("st.global.cs.v2.u64 [%0], {%1, %2};" :: "l"(p), "l"(a), "l"(b) : "memory");
}
__device__ __forceinline__ float4 ld4(const float* p) {
    return *reinterpret_cast<const float4*>(p);
}
__device__ __forceinline__ unsigned smem_u32(const void* p) {
    unsigned a;
    asm("{ .reg .u64 t; cvta.to.shared.u64 t, %1; cvt.u32.u64 %0, t; }" : "=r"(a) : "l"(p));
    return a;
}
__device__ __forceinline__ void cpasync4(unsigned dst, const float* src) {
    asm volatile("cp.async.ca.shared.global [%0], [%1], 4;" :: "r"(dst), "l"(src));
}

// ---------------------------------------------------------------------------
// kb precompute: 2 rows per 256-thread block.
// ---------------------------------------------------------------------------
__global__ __launch_bounds__(256) void kbkern(
    const float* __restrict__ seq, const float* __restrict__ Wk,
    const float* __restrict__ bk,  const float* __restrict__ bpos)
{
    const int tid = threadIdx.x;
    const int rr  = tid >> 7;
    const int c   = tid & 127;
    const int i   = blockIdx.x * 2 + rr;

    __shared__ float s[2][SEQD];
    if (tid < 2 * SEQD)
        s[tid / SEQD][tid % SEQD] = seq[(blockIdx.x * 2 + tid / SEQD) * SEQD + tid % SEQD];
    __syncthreads();

    float a = bk[c] + bpos[c];
    #pragma unroll
    for (int d = 0; d < SEQD; d++) a += s[rr][d] * Wk[d * ZD + c];
    g_kb[i * ZD + c] = a;
}

// ---------------------------------------------------------------------------
// issue cp.async fill of one m-unit's msa slice into a smem buffer
// ---------------------------------------------------------------------------
__device__ __forceinline__ void fill_unit(int u, float* dst,
                                          const float* __restrict__ msa, int tid)
{
    const int l  = u >> 2;
    const int n0 = (u & 3) * MU_ROWS;
    for (int idx = tid; idx < MU_ROWS * MSAD; idx += 128) {
        const int nl = idx / MSAD;        // 0..63 local row
        const int k  = idx - nl * MSAD;
        const unsigned d = smem_u32(&dst[(nl >> 1) * PSTRIDE + 2 * k + (nl & 1)]);
        cpasync4(d, &msa[((long)(n0 + nl) * LSEQ + l) * MSAD + k]);
    }
}

// ---------------------------------------------------------------------------
// Persistent fused kernel: 592 blocks x 128 threads; static unit list.
// ---------------------------------------------------------------------------
__global__ __launch_bounds__(128, 4) void mainkern(
    const float* __restrict__ seq,  const float* __restrict__ msa,
    const float* __restrict__ Wmsa, const float* __restrict__ bmsa,
    const float* __restrict__ Ws,   const float* __restrict__ bs,
    const float* __restrict__ Wq,   const float* __restrict__ bq,
    const float* __restrict__ Wpos, const float* __restrict__ Wpos2,
    const float* __restrict__ bpos2,
    float* __restrict__ outm, float* __restrict__ outz)
{
    const int tid = threadIdx.x;
    const int bc  = blockIdx.x;
    const int cnt   = (bc < 224) ? 11 : 10;
    const int start = (bc < 224) ? bc * 11 : 224 * 11 + (bc - 224) * 10;
    const int endg  = start + cnt;

    __shared__ float bufs[2][NPAIR * PSTRIDE];   // 2 x 6.1 KB

    // prefill the first m-unit in range
    int fillpar = 0;
    {
        const int g0 = (start & 1) ? start + 1 : start;
        if (g0 < endg) {
            fill_unit(g0 >> 1, bufs[0], msa, tid);
            fillpar = 1;
        }
    }
    asm volatile("cp.async.commit_group;" ::: "memory");

    int mpar = 0;
    for (int s = 0; s < cnt; s++) {
        const int g = start + s;

        if (g & 1) {
            // ---------- z-unit: z[i,j,:] = sq[j] + kb[i] + Wpos[rel] --------
            const int v  = g >> 1;            // 0..3071
            const int j  = (v >> 4) * 4 + (tid >> 5);
            const int i0 = (v & 15) * ZCH;
            const int c  = (tid & 31) * 4;

            float4 q;
            q.x = bq[c]; q.y = bq[c + 1]; q.z = bq[c + 2]; q.w = bq[c + 3];
            #pragma unroll
            for (int d = 0; d < SEQD; d++) {
                const float  sv = seq[j * SEQD + d];
                const float4 w  = ld4(Wq + d * ZD + c);
                q.x += sv * w.x; q.y += sv * w.y; q.z += sv * w.z; q.w += sv * w.w;
            }
            const ull q01 = pk2(q.x, q.y);
            const ull q23 = pk2(q.z, q.w);

            for (int ib = i0; ib < i0 + ZCH; ib += 8) {
                ulonglong2 kbv[8];
                #pragma unroll
                for (int u = 0; u < 8; u++)
                    kbv[u] = *reinterpret_cast<const ulonglong2*>(&g_kb[(ib + u) * ZD + c]);
                #pragma unroll
                for (int u = 0; u < 8; u++) {
                    const int i = ib + u;
                    int rel = j - i;
                    rel = min(max(rel, -RC), RC) + RC;
                    const ulonglong2 wp = *reinterpret_cast<const ulonglong2*>(&Wpos[rel * ZD + c]);
                    const ull o01 = add2(add2(q01, kbv[u].x), wp.x);
                    const ull o23 = add2(add2(q23, kbv[u].y), wp.y);
                    st2cs(&outz[((long)i * LSEQ + j) * ZD + c], o01, o23);
                }
            }
            continue;
        }

        // ---------- m-unit: m[n,l,:] = msa[n,l,:]@Wmsa + sp[l,:] ------------
        const int u  = g >> 1;                // 0..3071
        const int l  = u >> 2;
        const int n0 = (u & 3) * MU_ROWS;
        const int rg = tid >> 6;              // 0..1
        const int c  = (tid & 63) * 4;

        // wait for this unit's fill; sync so the buffer we are about to
        // refill (for the NEXT m-unit) is no longer being read by anyone.
        asm volatile("cp.async.wait_group 0;" ::: "memory");
        __syncthreads();

        // issue next m-unit's fill into the other buffer (hidden by the
        // z-unit between them + this unit's compute)
        if (g + 2 < endg) {
            fill_unit((g + 2) >> 1, bufs[fillpar], msa, tid);
            fillpar ^= 1;
        }
        asm volatile("cp.async.commit_group;" ::: "memory");

        // per-thread weights, channel-packed f32x2 (L1-hot reload per unit)
        ull w0[MSAD], w1[MSAD];
        #pragma unroll
        for (int k = 0; k < MSAD; k++) {
            const float4 w = ld4(Wmsa + k * MD + c);
            w0[k] = pk2(w.x, w.y);
            w1[k] = pk2(w.z, w.w);
        }

        // sp[l, c..c+3]
        float4 sp;
        sp.x = bs[c]     + bpos2[c]     + bmsa[c];
        sp.y = bs[c + 1] + bpos2[c + 1] + bmsa[c + 1];
        sp.z = bs[c + 2] + bpos2[c + 2] + bmsa[c + 2];
        sp.w = bs[c + 3] + bpos2[c + 3] + bmsa[c + 3];
        #pragma unroll
        for (int d = 0; d < SEQD; d++) {
            const float  sv = __ldg(&seq[l * SEQD + d]);
            const float4 w  = ld4(Ws + d * MD + c);
            sp.x += sv * w.x; sp.y += sv * w.y; sp.z += sv * w.z; sp.w += sv * w.w;
        }
        #pragma unroll
        for (int bb = 0; bb < NB; bb++)
            if ((l >> bb) & 1) {
                const float4 w = ld4(Wpos2 + bb * MD + c);
                sp.x += w.x; sp.y += w.y; sp.z += w.z; sp.w += w.w;
            }
        const ull sp01 = pk2(sp.x, sp.y);
        const ull sp23 = pk2(sp.z, sp.w);

        const float* mybuf = bufs[mpar];
        mpar ^= 1;

        // inner loop: one row-PAIR per iteration, 4 independent fma2 chains
        for (int it = 0; it < NPAIR / 2; it++) {
            const int p  = it * 2 + rg;       // local pair 0..31
            const int na = n0 + p * 2;        // global rows na, na+1
            const float* base = &mybuf[p * PSTRIDE];

            ull a01 = sp01, a23 = sp23;
            ull b01 = sp01, b23 = sp23;
            #pragma unroll
            for (int k = 0; k < MSAD; k++) {
                const float2 v = *reinterpret_cast<const float2*>(base + 2 * k);  // LDS.64
                const ull pa = dup2(v.x);
                const ull pb = dup2(v.y);
                a01 = fma2(w0[k], pa, a01);
                a23 = fma2(w1[k], pa, a23);
                b01 = fma2(w0[k], pb, b01);
                b23 = fma2(w1[k], pb, b23);
            }
            st2cs(&outm[((long)na * LSEQ + l) * MD + c], a01, a23);
            st2cs(&outm[((long)(na + 1) * LSEQ + l) * MD + c], b01, b23);
        }
    }
}

// ---------------------------------------------------------------------------
extern "C" void kernel_launch(void* const* d_in, const int* in_sizes, int n_in,
                              void* d_out, int out_size)
{
    const float* seq   = (const float*)d_in[0];
    const float* msa   = (const float*)d_in[1];
    const float* Wmsa  = (const float*)d_in[2];
    const float* bmsa  = (const float*)d_in[3];
    const float* Ws    = (const float*)d_in[4];
    const float* bs    = (const float*)d_in[5];
    const float* Wq    = (const float*)d_in[6];
    const float* bq    = (const float*)d_in[7];
    const float* Wk    = (const float*)d_in[8];
    const float* bk    = (const float*)d_in[9];
    const float* Wpos  = (const float*)d_in[10];
    const float* bpos  = (const float*)d_in[11];
    const float* Wpos2 = (const float*)d_in[12];
    const float* bpos2 = (const float*)d_in[13];

    float* outm = (float*)d_out;
    float* outz = outm + (long)NSEQ * LSEQ * MD;

    kbkern<<<LSEQ / 2, 256>>>(seq, Wk, bk, bpos);
    mainkern<<<NCTA, 128>>>(seq, msa, Wmsa, bmsa, Ws, bs, Wq, bq,
                            Wpos, Wpos2, bpos2, outm, outz);
}

// round 10
// speedup vs baseline: 1.1846x; 1.1037x over previous
#include <cuda_runtime.h>

#define LSEQ 768
#define NSEQ 256
#define MD   256
#define MSAD 23
#define SEQD 22
#define ZD   128
#define NB   14
#define RC   32
#define PSTRIDE 48    // floats per row-pair in smem: 23 k * 2 + pad

// Scratch: kb[i,:] = seq@Wk + bk + bpos  (384 KB)
__device__ float g_kb[LSEQ * ZD];

// ---- packed f32x2 helpers (sm_103a, PTX-only) ----
typedef unsigned long long ull;
__device__ __forceinline__ ull pk2(float a, float b) {
    ull r; asm("mov.b64 %0, {%1, %2};" : "=l"(r) : "f"(a), "f"(b)); return r;
}
__device__ __forceinline__ ull dup2(float a) {
    ull r; asm("mov.b64 %0, {%1, %1};" : "=l"(r) : "f"(a)); return r;
}
__device__ __forceinline__ ull fma2(ull a, ull b, ull c) {
    ull d; asm("fma.rn.f32x2 %0, %1, %2, %3;" : "=l"(d) : "l"(a), "l"(b), "l"(c));
    return d;
}
__device__ __forceinline__ ull add2(ull a, ull b) {
    ull d; asm("add.rn.f32x2 %0, %1, %2;" : "=l"(d) : "l"(a), "l"(b)); return d;
}
__device__ __forceinline__ void st2cs(float* p, ull a, ull b) {
    asm volatile("st.global.cs.v2.u64 [%0], {%1, %2};" :: "l"(p), "l"(a), "l"(b) : "memory");
}
__device__ __forceinline__ float4 ld4(const float* p) {
    return *reinterpret_cast<const float4*>(p);
}
__device__ __forceinline__ unsigned smem_u32(const void* p) {
    unsigned a;
    asm("{ .reg .u64 t; cvta.to.shared.u64 t, %1; cvt.u32.u64 %0, t; }" : "=r"(a) : "l"(p));
    return a;
}
__device__ __forceinline__ void cpasync4(unsigned dst, const float* src) {
    asm volatile("cp.async.ca.shared.global [%0], [%1], 4;" :: "r"(dst), "l"(src));
}

// ---------------------------------------------------------------------------
// kb precompute: 2 rows per 256-thread block.
// ---------------------------------------------------------------------------
__global__ __launch_bounds__(256) void kbkern(
    const float* __restrict__ seq, const float* __restrict__ Wk,
    const float* __restrict__ bk,  const float* __restrict__ bpos)
{
    const int tid = threadIdx.x;
    const int rr  = tid >> 7;
    const int c   = tid & 127;
    const int i   = blockIdx.x * 2 + rr;

    __shared__ float s[2][SEQD];
    if (tid < 2 * SEQD)
        s[tid / SEQD][tid % SEQD] = seq[(blockIdx.x * 2 + tid / SEQD) * SEQD + tid % SEQD];
    __syncthreads();

    float a = bk[c] + bpos[c];
    #pragma unroll
    for (int d = 0; d < SEQD; d++) a += s[rr][d] * Wk[d * ZD + c];
    g_kb[i * ZD + c] = a;
}

// constant-rel z segment: o = const + kb[i], batched x8 for MLP
__device__ __forceinline__ void zconst(int ia, int ib, int c, int j,
                                       ull k01, ull k23, float* __restrict__ outz)
{
    const long zs = (long)LSEQ * ZD;
    int i = ia;
    for (; i + 8 <= ib; i += 8) {
        ulonglong2 kv[8];
        #pragma unroll
        for (int u = 0; u < 8; u++)
            kv[u] = *reinterpret_cast<const ulonglong2*>(&g_kb[(i + u) * ZD + c]);
        #pragma unroll
        for (int u = 0; u < 8; u++)
            st2cs(&outz[(i + u) * zs + (long)j * ZD + c],
                  add2(k01, kv[u].x), add2(k23, kv[u].y));
    }
    for (; i < ib; i++) {
        const ulonglong2 kv = *reinterpret_cast<const ulonglong2*>(&g_kb[i * ZD + c]);
        st2cs(&outz[i * zs + (long)j * ZD + c], add2(k01, kv.x), add2(k23, kv.y));
    }
}

// ---------------------------------------------------------------------------
// Fused main kernel: 1536 blocks x 128 threads, strict 1:1 interleave.
//   b & 1 == 0 -> m-path (l = b>>1, all 256 rows)
//   b & 1 == 1 -> z-path (4 j's, quarter of the i range)
// ---------------------------------------------------------------------------
__global__ __launch_bounds__(128, 4) void mainkern(
    const float* __restrict__ seq,  const float* __restrict__ msa,
    const float* __restrict__ Wmsa, const float* __restrict__ bmsa,
    const float* __restrict__ Ws,   const float* __restrict__ bs,
    const float* __restrict__ Wq,   const float* __restrict__ bq,
    const float* __restrict__ Wpos, const float* __restrict__ Wpos2,
    const float* __restrict__ bpos2,
    float* __restrict__ outm, float* __restrict__ outz)
{
    const int b   = blockIdx.x;
    const int tid = threadIdx.x;

    if (b & 1) {
        // ------------- z-path: z[i,j,:] = sq[j] + kb[i] + Wpos[rel] ---------
        // rel = clip(j-i, +-32)+32 is CONSTANT (64 or 0) outside |j-i|<=32.
        const int zid = b >> 1;           // 0..767
        const int j   = (zid >> 2) * 4 + (tid >> 5);
        const int iq  = zid & 3;          // i-quarter
        const int c   = (tid & 31) * 4;

        float4 q;
        q.x = bq[c]; q.y = bq[c + 1]; q.z = bq[c + 2]; q.w = bq[c + 3];
        #pragma unroll
        for (int d = 0; d < SEQD; d++) {
            const float  sv = seq[j * SEQD + d];
            const float4 w  = ld4(Wq + d * ZD + c);
            q.x += sv * w.x; q.y += sv * w.y; q.z += sv * w.z; q.w += sv * w.w;
        }
        const ull q01 = pk2(q.x, q.y);
        const ull q23 = pk2(q.z, q.w);

        // fold q + clamped Wpos into registers
        const ulonglong2 wpHI = *reinterpret_cast<const ulonglong2*>(&Wpos[64 * ZD + c]); // i < j-32
        const ulonglong2 wpLO = *reinterpret_cast<const ulonglong2*>(&Wpos[c]);           // i > j+32
        const ull hi01 = add2(q01, wpHI.x), hi23 = add2(q23, wpHI.y);
        const ull lo01 = add2(q01, wpLO.x), lo23 = add2(q23, wpLO.y);

        const int i0   = iq * (LSEQ / 4);
        const int iend = i0 + LSEQ / 4;
        const int sA   = min(max(j - 32, i0), iend);   // end of rel=64 region
        const int sB   = min(max(j + 33, i0), iend);   // start of rel=0 region

        zconst(i0, sA, c, j, hi01, hi23, outz);        // i < j-32

        const long zs = (long)LSEQ * ZD;
        #pragma unroll 2
        for (int i = sA; i < sB; i++) {                // |j-i| <= 32, rel in range
            const int rel = j - i + RC;
            const ulonglong2 kv = *reinterpret_cast<const ulonglong2*>(&g_kb[i * ZD + c]);
            const ulonglong2 wp = *reinterpret_cast<const ulonglong2*>(&Wpos[rel * ZD + c]);
            st2cs(&outz[i * zs + (long)j * ZD + c],
                  add2(add2(q01, kv.x), wp.x), add2(add2(q23, kv.y), wp.y));
        }

        zconst(sB, iend, c, j, lo01, lo23, outz);      // i > j+32
        return;
    }

    // ------------ m-path: m[n,l,:] = msa[n,l,:]@Wmsa + sp[l,:] --------------
    const int l  = b >> 1;                // 0..767
    const int rg = tid >> 6;              // 0..1
    const int c  = (tid & 63) * 4;

    // Row-PAIR interleaved layout: pairs[p][k][s] = msa[2p+s, l, k]
    __shared__ float pairs[(NSEQ / 2) * PSTRIDE];   // 24.6 KB
    __shared__ float srow[SEQD];

    if (tid < SEQD) srow[tid] = seq[l * SEQD + tid];
    // cp.async fill: 46 outstanding 4B copies per thread, no reg round-trip
    for (int idx = tid; idx < NSEQ * MSAD; idx += 128) {
        const int n = idx / MSAD;
        const int k = idx - n * MSAD;
        const unsigned dst = smem_u32(&pairs[(n >> 1) * PSTRIDE + 2 * k + (n & 1)]);
        cpasync4(dst, &msa[(n * LSEQ + l) * MSAD + k]);
    }
    asm volatile("cp.async.commit_group;" ::: "memory");

    // per-thread weights, channel-packed f32x2 (92 regs) — overlaps cp.async
    ull w0[MSAD], w1[MSAD];
    #pragma unroll
    for (int k = 0; k < MSAD; k++) {
        const float4 w = ld4(Wmsa + k * MD + c);
        w0[k] = pk2(w.x, w.y);
        w1[k] = pk2(w.z, w.w);
    }

    // sp[l, c..c+3]
    float4 sp;
    sp.x = bs[c]     + bpos2[c]     + bmsa[c];
    sp.y = bs[c + 1] + bpos2[c + 1] + bmsa[c + 1];
    sp.z = bs[c + 2] + bpos2[c + 2] + bmsa[c + 2];
    sp.w = bs[c + 3] + bpos2[c + 3] + bmsa[c + 3];
    #pragma unroll
    for (int bb = 0; bb < NB; bb++)
        if ((l >> bb) & 1) {
            const float4 w = ld4(Wpos2 + bb * MD + c);
            sp.x += w.x; sp.y += w.y; sp.z += w.z; sp.w += w.w;
        }
    asm volatile("cp.async.wait_group 0;" ::: "memory");
    __syncthreads();
    #pragma unroll
    for (int d = 0; d < SEQD; d++) {
        const float  sv = srow[d];
        const float4 w  = ld4(Ws + d * MD + c);
        sp.x += sv * w.x; sp.y += sv * w.y; sp.z += sv * w.z; sp.w += sv * w.w;
    }
    const ull sp01 = pk2(sp.x, sp.y);
    const ull sp23 = pk2(sp.z, sp.w);

    // main loop: one row-PAIR per iteration -> 4 independent fma2 chains,
    // 23 LDS.64 per pair.
    for (int it = 0; it < NSEQ / 4; it++) {
        const int p  = it * 2 + rg;       // pair index 0..127
        const int na = p * 2;             // rows na, na+1
        const float* base = &pairs[p * PSTRIDE];

        ull a01 = sp01, a23 = sp23;       // row na
        ull b01 = sp01, b23 = sp23;       // row na+1
        #pragma unroll
        for (int k = 0; k < MSAD; k++) {
            const float2 v = *reinterpret_cast<const float2*>(base + 2 * k);  // LDS.64
            const ull pa = dup2(v.x);
            const ull pb = dup2(v.y);
            a01 = fma2(w0[k], pa, a01);
            a23 = fma2(w1[k], pa, a23);
            b01 = fma2(w0[k], pb, b01);
            b23 = fma2(w1[k], pb, b23);
        }
        st2cs(&outm[((long)na * LSEQ + l) * MD + c], a01, a23);
        st2cs(&outm[((long)(na + 1) * LSEQ + l) * MD + c], b01, b23);
    }
}

// ---------------------------------------------------------------------------
extern "C" void kernel_launch(void* const* d_in, const int* in_sizes, int n_in,
                              void* d_out, int out_size)
{
    const float* seq   = (const float*)d_in[0];
    const float* msa   = (const float*)d_in[1];
    const float* Wmsa  = (const float*)d_in[2];
    const float* bmsa  = (const float*)d_in[3];
    const float* Ws    = (const float*)d_in[4];
    const float* bs    = (const float*)d_in[5];
    const float* Wq    = (const float*)d_in[6];
    const float* bq    = (const float*)d_in[7];
    const float* Wk    = (const float*)d_in[8];
    const float* bk    = (const float*)d_in[9];
    const float* Wpos  = (const float*)d_in[10];
    const float* bpos  = (const float*)d_in[11];
    const float* Wpos2 = (const float*)d_in[12];
    const float* bpos2 = (const float*)d_in[13];

    float* outm = (float*)d_out;
    float* outz = outm + (long)NSEQ * LSEQ * MD;

    kbkern<<<LSEQ / 2, 256>>>(seq, Wk, bk, bpos);
    mainkern<<<1536, 128>>>(seq, msa, Wmsa, bmsa, Ws, bs, Wq, bq,
                            Wpos, Wpos2, bpos2, outm, outz);
}

// round 11
// speedup vs baseline: 1.1929x; 1.0070x over previous
#include <cuda_runtime.h>

#define LSEQ 768
#define NSEQ 256
#define MD   256
#define MSAD 23
#define SEQD 22
#define ZD   128
#define NB   14
#define RC   32
#define PSTRIDE 48    // floats per row-pair in smem: 23 k * 2 + pad

// Scratch: kb[i,:] = seq@Wk + bk + bpos  (384 KB)
__device__ float g_kb[LSEQ * ZD];

// ---- packed f32x2 helpers (sm_103a, PTX-only) ----
typedef unsigned long long ull;
__device__ __forceinline__ ull pk2(float a, float b) {
    ull r; asm("mov.b64 %0, {%1, %2};" : "=l"(r) : "f"(a), "f"(b)); return r;
}
__device__ __forceinline__ ull dup2(float a) {
    ull r; asm("mov.b64 %0, {%1, %1};" : "=l"(r) : "f"(a)); return r;
}
__device__ __forceinline__ ull fma2(ull a, ull b, ull c) {
    ull d; asm("fma.rn.f32x2 %0, %1, %2, %3;" : "=l"(d) : "l"(a), "l"(b), "l"(c));
    return d;
}
__device__ __forceinline__ ull add2(ull a, ull b) {
    ull d; asm("add.rn.f32x2 %0, %1, %2;" : "=l"(d) : "l"(a), "l"(b)); return d;
}
__device__ __forceinline__ void st2cs(float* p, ull a, ull b) {
    asm volatile("st.global.cs.v2.u64 [%0], {%1, %2};" :: "l"(p), "l"(a), "l"(b) : "memory");
}
__device__ __forceinline__ float4 ld4(const float* p) {
    return *reinterpret_cast<const float4*>(p);
}
__device__ __forceinline__ unsigned smem_u32(const void* p) {
    unsigned a;
    asm("{ .reg .u64 t; cvta.to.shared.u64 t, %1; cvt.u32.u64 %0, t; }" : "=r"(a) : "l"(p));
    return a;
}
__device__ __forceinline__ void cpasync4(unsigned dst, const float* src) {
    asm volatile("cp.async.ca.shared.global [%0], [%1], 4;" :: "r"(dst), "l"(src));
}

// ---------------------------------------------------------------------------
// kb precompute: 2 rows per 256-thread block.
// ---------------------------------------------------------------------------
__global__ __launch_bounds__(256) void kbkern(
    const float* __restrict__ seq, const float* __restrict__ Wk,
    const float* __restrict__ bk,  const float* __restrict__ bpos)
{
    const int tid = threadIdx.x;
    const int rr  = tid >> 7;
    const int c   = tid & 127;
    const int i   = blockIdx.x * 2 + rr;

    __shared__ float s[2][SEQD];
    if (tid < 2 * SEQD)
        s[tid / SEQD][tid % SEQD] = seq[(blockIdx.x * 2 + tid / SEQD) * SEQD + tid % SEQD];
    __syncthreads();

    float a = bk[c] + bpos[c];
    #pragma unroll
    for (int d = 0; d < SEQD; d++) a += s[rr][d] * Wk[d * ZD + c];
    g_kb[i * ZD + c] = a;
}

// constant-rel z segment: o = const + kb[i], batched x8 for MLP
__device__ __forceinline__ void zconst(int ia, int ib, int c, int j,
                                       ull k01, ull k23, float* __restrict__ outz)
{
    const long zs = (long)LSEQ * ZD;
    int i = ia;
    for (; i + 8 <= ib; i += 8) {
        ulonglong2 kv[8];
        #pragma unroll
        for (int u = 0; u < 8; u++)
            kv[u] = *reinterpret_cast<const ulonglong2*>(&g_kb[(i + u) * ZD + c]);
        #pragma unroll
        for (int u = 0; u < 8; u++)
            st2cs(&outz[(i + u) * zs + (long)j * ZD + c],
                  add2(k01, kv[u].x), add2(k23, kv[u].y));
    }
    for (; i < ib; i++) {
        const ulonglong2 kv = *reinterpret_cast<const ulonglong2*>(&g_kb[i * ZD + c]);
        st2cs(&outz[i * zs + (long)j * ZD + c], add2(k01, kv.x), add2(k23, kv.y));
    }
}

// ---------------------------------------------------------------------------
// Fused main kernel: 1536 blocks x 128 threads.
// Type selector: groups of 4 bids alternate m/z. Same-SM resident bids differ
// by 148 -> group index differs by 37 (odd) -> each SM co-hosts BOTH types
// (the bid&1 selector made every SM type-homogeneous, since 148 is even).
//   g = b>>2; g even -> m-path, g odd -> z-path; rank = (g>>1)*4 + (b&3).
// ---------------------------------------------------------------------------
__global__ __launch_bounds__(128, 4) void mainkern(
    const float* __restrict__ seq,  const float* __restrict__ msa,
    const float* __restrict__ Wmsa, const float* __restrict__ bmsa,
    const float* __restrict__ Ws,   const float* __restrict__ bs,
    const float* __restrict__ Wq,   const float* __restrict__ bq,
    const float* __restrict__ Wpos, const float* __restrict__ Wpos2,
    const float* __restrict__ bpos2,
    float* __restrict__ outm, float* __restrict__ outz)
{
    const int b    = blockIdx.x;
    const int tid  = threadIdx.x;
    const int grp  = b >> 2;
    const int rank = (grp >> 1) * 4 + (b & 3);   // 0..767 within type

    if (grp & 1) {
        // ------------- z-path: z[i,j,:] = sq[j] + kb[i] + Wpos[rel] ---------
        // rel = clip(j-i, +-32)+32 is CONSTANT (64 or 0) outside |j-i|<=32.
        const int zid = rank;             // 0..767
        const int j   = (zid >> 2) * 4 + (tid >> 5);
        const int iq  = zid & 3;          // i-quarter
        const int c   = (tid & 31) * 4;

        float4 q;
        q.x = bq[c]; q.y = bq[c + 1]; q.z = bq[c + 2]; q.w = bq[c + 3];
        #pragma unroll
        for (int d = 0; d < SEQD; d++) {
            const float  sv = seq[j * SEQD + d];
            const float4 w  = ld4(Wq + d * ZD + c);
            q.x += sv * w.x; q.y += sv * w.y; q.z += sv * w.z; q.w += sv * w.w;
        }
        const ull q01 = pk2(q.x, q.y);
        const ull q23 = pk2(q.z, q.w);

        // fold q + clamped Wpos into registers
        const ulonglong2 wpHI = *reinterpret_cast<const ulonglong2*>(&Wpos[64 * ZD + c]); // i < j-32
        const ulonglong2 wpLO = *reinterpret_cast<const ulonglong2*>(&Wpos[c]);           // i > j+32
        const ull hi01 = add2(q01, wpHI.x), hi23 = add2(q23, wpHI.y);
        const ull lo01 = add2(q01, wpLO.x), lo23 = add2(q23, wpLO.y);

        const int i0   = iq * (LSEQ / 4);
        const int iend = i0 + LSEQ / 4;
        const int sA   = min(max(j - 32, i0), iend);   // end of rel=64 region
        const int sB   = min(max(j + 33, i0), iend);   // start of rel=0 region

        zconst(i0, sA, c, j, hi01, hi23, outz);        // i < j-32

        const long zs = (long)LSEQ * ZD;
        #pragma unroll 2
        for (int i = sA; i < sB; i++) {                // |j-i| <= 32, rel in range
            const int rel = j - i + RC;
            const ulonglong2 kv = *reinterpret_cast<const ulonglong2*>(&g_kb[i * ZD + c]);
            const ulonglong2 wp = *reinterpret_cast<const ulonglong2*>(&Wpos[rel * ZD + c]);
            st2cs(&outz[i * zs + (long)j * ZD + c],
                  add2(add2(q01, kv.x), wp.x), add2(add2(q23, kv.y), wp.y));
        }

        zconst(sB, iend, c, j, lo01, lo23, outz);      // i > j+32
        return;
    }

    // ------------ m-path: m[n,l,:] = msa[n,l,:]@Wmsa + sp[l,:] --------------
    const int l  = rank;                  // 0..767
    const int rg = tid >> 6;              // 0..1
    const int c  = (tid & 63) * 4;

    // Row-PAIR interleaved layout: pairs[p][k][s] = msa[2p+s, l, k]
    __shared__ float pairs[(NSEQ / 2) * PSTRIDE];   // 24.6 KB
    __shared__ float srow[SEQD];

    if (tid < SEQD) srow[tid] = seq[l * SEQD + tid];
    // cp.async fill: 46 outstanding 4B copies per thread, no reg round-trip
    for (int idx = tid; idx < NSEQ * MSAD; idx += 128) {
        const int n = idx / MSAD;
        const int k = idx - n * MSAD;
        const unsigned dst = smem_u32(&pairs[(n >> 1) * PSTRIDE + 2 * k + (n & 1)]);
        cpasync4(dst, &msa[(n * LSEQ + l) * MSAD + k]);
    }
    asm volatile("cp.async.commit_group;" ::: "memory");

    // per-thread weights, channel-packed f32x2 (92 regs) — overlaps cp.async
    ull w0[MSAD], w1[MSAD];
    #pragma unroll
    for (int k = 0; k < MSAD; k++) {
        const float4 w = ld4(Wmsa + k * MD + c);
        w0[k] = pk2(w.x, w.y);
        w1[k] = pk2(w.z, w.w);
    }

    // sp[l, c..c+3]
    float4 sp;
    sp.x = bs[c]     + bpos2[c]     + bmsa[c];
    sp.y = bs[c + 1] + bpos2[c + 1] + bmsa[c + 1];
    sp.z = bs[c + 2] + bpos2[c + 2] + bmsa[c + 2];
    sp.w = bs[c + 3] + bpos2[c + 3] + bmsa[c + 3];
    #pragma unroll
    for (int bb = 0; bb < NB; bb++)
        if ((l >> bb) & 1) {
            const float4 w = ld4(Wpos2 + bb * MD + c);
            sp.x += w.x; sp.y += w.y; sp.z += w.z; sp.w += w.w;
        }
    asm volatile("cp.async.wait_group 0;" ::: "memory");
    __syncthreads();
    #pragma unroll
    for (int d = 0; d < SEQD; d++) {
        const float  sv = srow[d];
        const float4 w  = ld4(Ws + d * MD + c);
        sp.x += sv * w.x; sp.y += sv * w.y; sp.z += sv * w.z; sp.w += sv * w.w;
    }
    const ull sp01 = pk2(sp.x, sp.y);
    const ull sp23 = pk2(sp.z, sp.w);

    // main loop: one row-PAIR per iteration -> 4 independent fma2 chains,
    // 23 LDS.64 per pair.
    for (int it = 0; it < NSEQ / 4; it++) {
        const int p  = it * 2 + rg;       // pair index 0..127
        const int na = p * 2;             // rows na, na+1
        const float* base = &pairs[p * PSTRIDE];

        ull a01 = sp01, a23 = sp23;       // row na
        ull b01 = sp01, b23 = sp23;       // row na+1
        #pragma unroll
        for (int k = 0; k < MSAD; k++) {
            const float2 v = *reinterpret_cast<const float2*>(base + 2 * k);  // LDS.64
            const ull pa = dup2(v.x);
            const ull pb = dup2(v.y);
            a01 = fma2(w0[k], pa, a01);
            a23 = fma2(w1[k], pa, a23);
            b01 = fma2(w0[k], pb, b01);
            b23 = fma2(w1[k], pb, b23);
        }
        st2cs(&outm[((long)na * LSEQ + l) * MD + c], a01, a23);
        st2cs(&outm[((long)(na + 1) * LSEQ + l) * MD + c], b01, b23);
    }
}

// ---------------------------------------------------------------------------
extern "C" void kernel_launch(void* const* d_in, const int* in_sizes, int n_in,
                              void* d_out, int out_size)
{
    const float* seq   = (const float*)d_in[0];
    const float* msa   = (const float*)d_in[1];
    const float* Wmsa  = (const float*)d_in[2];
    const float* bmsa  = (const float*)d_in[3];
    const float* Ws    = (const float*)d_in[4];
    const float* bs    = (const float*)d_in[5];
    const float* Wq    = (const float*)d_in[6];
    const float* bq    = (const float*)d_in[7];
    const float* Wk    = (const float*)d_in[8];
    const float* bk    = (const float*)d_in[9];
    const float* Wpos  = (const float*)d_in[10];
    const float* bpos  = (const float*)d_in[11];
    const float* Wpos2 = (const float*)d_in[12];
    const float* bpos2 = (const float*)d_in[13];

    float* outm = (float*)d_out;
    float* outz = outm + (long)NSEQ * LSEQ * MD;

    kbkern<<<LSEQ / 2, 256>>>(seq, Wk, bk, bpos);
    mainkern<<<1536, 128>>>(seq, msa, Wmsa, bmsa, Ws, bs, Wq, bq,
                            Wpos, Wpos2, bpos2, outm, outz);
}